// round 13
// baseline (speedup 1.0000x reference)
#include <cuda_runtime.h>
#include <math.h>

#define BATCH 2
#define CIN   256
#define HH    128
#define WW    128
#define OUTC  256
#define HWN   (HH*WW)

// ---------------- device scratch (no allocations allowed) -------------------
__device__ __align__(16) float  g_xT [BATCH*HWN*CIN];   // x as [b][y][x][c]
__device__ __align__(16) float  g_tmp[BATCH*27*HWN];    // offset conv out [b][27][hw]
__device__ __align__(16) float  g_agg[BATCH*HWN*CIN];   // Sum_k mask*sample [b][hw][c]
__device__ float2 g_mstat[BATCH*9];                     // per (b,k): {rowmax, 1/sum}

// ---------------- 1) NCHW -> NHWC transpose ---------------------------------
__global__ void transpose_kernel(const float* __restrict__ x){
    __shared__ float tile[32][33];
    int b  = blockIdx.z >> 7;
    int y  = blockIdx.z & 127;
    int x0 = blockIdx.x * 32;
    int c0 = blockIdx.y * 32;
    int tx = threadIdx.x, ty = threadIdx.y;
    #pragma unroll
    for (int q = 0; q < 4; q++){
        int c = ty + q*8;                               // channel within tile
        tile[c][tx] = x[(((b*CIN + c0 + c)*HH + y) << 7) + x0 + tx];
    }
    __syncthreads();
    #pragma unroll
    for (int q = 0; q < 4; q++){
        int xi = ty + q*8;                              // x within tile
        // g_xT[b][y][x0+xi][c0+tx]
        g_xT[((((b*HH + y) << 7) + x0 + xi) << 8) + c0 + tx] = tile[tx][xi];
    }
}

// ---------------- 2) offset conv: 27 out ch, 3x3, pad 1 ---------------------
// one block = one (b, row); 128 threads = 128 pixels; loop C in chunks of 8
__global__ __launch_bounds__(128, 2)
void offs_conv_kernel(const float* __restrict__ x,
                      const float* __restrict__ w_off,
                      const float* __restrict__ b_off){
    __shared__ __align__(16) float sx[8][3][132];   // [c][row][x+1], halo cols
    __shared__ __align__(16) float sw[8][9][28];    // [c][tap][oc] padded to 28

    int y = blockIdx.x;
    int b = blockIdx.y;
    int t = threadIdx.x;                            // pixel x

    float acc[27];
    #pragma unroll
    for (int oc = 0; oc < 27; oc++) acc[oc] = __ldg(&b_off[oc]);

    for (int c0 = 0; c0 < CIN; c0 += 8){
        // stage input rows y-1..y+1, 8 channels, with zero halo
        for (int i = t; i < 8*3*130; i += 128){
            int xi  = i % 130;
            int rc  = i / 130;
            int row = rc % 3;
            int c   = rc / 3;
            int yy  = y - 1 + row;
            int xx  = xi - 1;
            float v = 0.f;
            if (yy >= 0 && yy < HH && xx >= 0 && xx < WW)
                v = x[(((b*CIN + c0 + c)*HH + yy) << 7) + xx];
            sx[c][row][xi] = v;
        }
        // stage weights: w_off[oc][c][tap]
        for (int e = t; e < 8*9*27; e += 128){
            int oc  = e % 27;
            int rr  = e / 27;
            int tap = rr % 9;
            int c   = rr / 9;
            sw[c][tap][oc] = w_off[((oc*CIN) + c0 + c)*9 + tap];
        }
        __syncthreads();

        #pragma unroll
        for (int c = 0; c < 8; c++){
            float v[9];
            #pragma unroll
            for (int ky = 0; ky < 3; ky++)
                #pragma unroll
                for (int kx = 0; kx < 3; kx++)
                    v[ky*3 + kx] = sx[c][ky][t + kx];
            #pragma unroll
            for (int tap = 0; tap < 9; tap++){
                #pragma unroll
                for (int q = 0; q < 7; q++){
                    float4 w4 = *(const float4*)&sw[c][tap][q*4];   // LDS.128 broadcast
                    acc[q*4 + 0] += v[tap]*w4.x;
                    if (q*4 + 1 < 27) acc[q*4 + 1] += v[tap]*w4.y;
                    if (q*4 + 2 < 27) acc[q*4 + 2] += v[tap]*w4.z;
                    if (q*4 + 3 < 27) acc[q*4 + 3] += v[tap]*w4.w;
                }
            }
        }
        __syncthreads();
    }

    #pragma unroll
    for (int oc = 0; oc < 27; oc++)
        g_tmp[((b*27 + oc) << 14) + (y << 7) + t] = acc[oc];
}

// ---------------- 3) softmax stats per (b,k) over HW -------------------------
__global__ void softmax_kernel(){
    __shared__ float red[256];
    int bi = blockIdx.x;                     // 0..17
    int t  = threadIdx.x;
    const float* row = g_tmp + (((bi/9)*27 + 18 + (bi%9)) << 14);
    float m = -1e30f;
    for (int i = t; i < HWN; i += 256) m = fmaxf(m, row[i]);
    red[t] = m; __syncthreads();
    for (int s = 128; s > 0; s >>= 1){
        if (t < s) red[t] = fmaxf(red[t], red[t+s]);
        __syncthreads();
    }
    float mx = red[0]; __syncthreads();
    float sacc = 0.f;
    for (int i = t; i < HWN; i += 256) sacc += expf(row[i] - mx);
    red[t] = sacc; __syncthreads();
    for (int s = 128; s > 0; s >>= 1){
        if (t < s) red[t] += red[t+s];
        __syncthreads();
    }
    if (t == 0) g_mstat[bi] = make_float2(mx, 1.0f / red[0]);
}

// ---------------- 4) bilinear sample + mask, summed over K ------------------
// one warp per output pixel; channels-last gathers (float4 per lane)
__global__ __launch_bounds__(256)
void sample_kernel(){
    int wid  = blockIdx.x * 8 + (threadIdx.x >> 5);
    int lane = threadIdx.x & 31;
    int b    = wid >> 14;
    int hw   = wid & 16383;
    int y    = hw >> 7, xx = hw & 127;

    // lane k (k<9) computes its tap's parameters
    int   cy0 = 0, cy1 = 0, cx0 = 0, cx1 = 0;
    float W00 = 0.f, W01 = 0.f, W10 = 0.f, W11 = 0.f;
    if (lane < 9){
        int base = (b*27) << 14;
        float dy = g_tmp[base + ((2*lane    ) << 14) + hw];
        float dx = g_tmp[base + ((2*lane + 1) << 14) + hw];
        float mr = g_tmp[base + ((18 + lane ) << 14) + hw];
        float2 st = g_mstat[b*9 + lane];
        float mask = expf(mr - st.x) * st.y;

        float py = dy + (float)(lane/3) - 1.0f + (float)y;
        float px = dx + (float)(lane%3) - 1.0f + (float)xx;
        float fy = floorf(py), fx = floorf(px);
        int   y0 = (int)fy,    x0 = (int)fx;
        float ly = py - fy,    lx = px - fx;

        bool vy0 = (y0 >= 0)     && (y0 < HH);
        bool vy1 = (y0+1 >= 0)   && (y0+1 < HH);
        bool vx0 = (x0 >= 0)     && (x0 < WW);
        bool vx1 = (x0+1 >= 0)   && (x0+1 < WW);

        W00 = (vy0 && vx0) ? (1.f-ly)*(1.f-lx)*mask : 0.f;
        W01 = (vy0 && vx1) ? (1.f-ly)*lx      *mask : 0.f;
        W10 = (vy1 && vx0) ? ly*(1.f-lx)      *mask : 0.f;
        W11 = (vy1 && vx1) ? ly*lx            *mask : 0.f;
        cy0 = min(max(y0,     0), HH-1);
        cy1 = min(max(y0 + 1, 0), HH-1);
        cx0 = min(max(x0,     0), WW-1);
        cx1 = min(max(x0 + 1, 0), WW-1);
    }

    float4 a0 = make_float4(0.f,0.f,0.f,0.f);
    float4 a1 = make_float4(0.f,0.f,0.f,0.f);
    const unsigned FULL = 0xffffffffu;
    int bbase = (b << 14);

    #pragma unroll
    for (int k = 0; k < 9; k++){
        int   ky0 = __shfl_sync(FULL, cy0, k);
        int   ky1 = __shfl_sync(FULL, cy1, k);
        int   kx0 = __shfl_sync(FULL, cx0, k);
        int   kx1 = __shfl_sync(FULL, cx1, k);
        float w00 = __shfl_sync(FULL, W00, k);
        float w01 = __shfl_sync(FULL, W01, k);
        float w10 = __shfl_sync(FULL, W10, k);
        float w11 = __shfl_sync(FULL, W11, k);

        int co = lane << 2;   // channel offset (floats)
        if (w00 != 0.f){
            const float* p = g_xT + (((bbase + (ky0<<7) + kx0)) << 8);
            float4 v0 = *(const float4*)(p + co);
            float4 v1 = *(const float4*)(p + 128 + co);
            a0.x += w00*v0.x; a0.y += w00*v0.y; a0.z += w00*v0.z; a0.w += w00*v0.w;
            a1.x += w00*v1.x; a1.y += w00*v1.y; a1.z += w00*v1.z; a1.w += w00*v1.w;
        }
        if (w01 != 0.f){
            const float* p = g_xT + (((bbase + (ky0<<7) + kx1)) << 8);
            float4 v0 = *(const float4*)(p + co);
            float4 v1 = *(const float4*)(p + 128 + co);
            a0.x += w01*v0.x; a0.y += w01*v0.y; a0.z += w01*v0.z; a0.w += w01*v0.w;
            a1.x += w01*v1.x; a1.y += w01*v1.y; a1.z += w01*v1.z; a1.w += w01*v1.w;
        }
        if (w10 != 0.f){
            const float* p = g_xT + (((bbase + (ky1<<7) + kx0)) << 8);
            float4 v0 = *(const float4*)(p + co);
            float4 v1 = *(const float4*)(p + 128 + co);
            a0.x += w10*v0.x; a0.y += w10*v0.y; a0.z += w10*v0.z; a0.w += w10*v0.w;
            a1.x += w10*v1.x; a1.y += w10*v1.y; a1.z += w10*v1.z; a1.w += w10*v1.w;
        }
        if (w11 != 0.f){
            const float* p = g_xT + (((bbase + (ky1<<7) + kx1)) << 8);
            float4 v0 = *(const float4*)(p + co);
            float4 v1 = *(const float4*)(p + 128 + co);
            a0.x += w11*v0.x; a0.y += w11*v0.y; a0.z += w11*v0.z; a0.w += w11*v0.w;
            a1.x += w11*v1.x; a1.y += w11*v1.y; a1.z += w11*v1.z; a1.w += w11*v1.w;
        }
    }

    float* dst = g_agg + ((size_t)wid << 8);
    *(float4*)(dst + (lane<<2))       = a0;
    *(float4*)(dst + 128 + (lane<<2)) = a1;
}

// ---------------- 5) 1x1 conv GEMM: out = W[256x256] * agg^T + bias ---------
// 64x64 tile per block, 4x4 per thread
__global__ __launch_bounds__(256)
void gemm_kernel(const float* __restrict__ weight,
                 const float* __restrict__ bias,
                 float* __restrict__ out){
    __shared__ __align__(16) float Ws[16][68];   // [kk][oo]
    __shared__ __align__(16) float As[16][68];   // [kk][nn]

    int o0 = blockIdx.x * 64;
    int n0 = blockIdx.y * 64;
    int b  = blockIdx.z;
    int tid = threadIdx.x;
    int tx = tid & 15;      // o-quad index
    int ty = tid >> 4;      // n-quad index

    float acc[4][4];
    #pragma unroll
    for (int i = 0; i < 4; i++)
        #pragma unroll
        for (int j = 0; j < 4; j++) acc[i][j] = 0.f;

    int lro = tid >> 2;           // 0..63 (row within tile)
    int lkb = (tid & 3) << 2;     // 0,4,8,12 (k sub-block)

    for (int c0 = 0; c0 < CIN; c0 += 16){
        float4 w4 = *(const float4*)&weight[(o0 + lro)*CIN + c0 + lkb];
        Ws[lkb+0][lro] = w4.x; Ws[lkb+1][lro] = w4.y;
        Ws[lkb+2][lro] = w4.z; Ws[lkb+3][lro] = w4.w;
        float4 a4 = *(const float4*)&g_agg[(size_t)((b<<14) + n0 + lro)*CIN + c0 + lkb];
        As[lkb+0][lro] = a4.x; As[lkb+1][lro] = a4.y;
        As[lkb+2][lro] = a4.z; As[lkb+3][lro] = a4.w;
        __syncthreads();

        #pragma unroll
        for (int kk = 0; kk < 16; kk++){
            float4 wv = *(const float4*)&Ws[kk][tx*4];
            float4 av = *(const float4*)&As[kk][ty*4];
            acc[0][0] += wv.x*av.x; acc[0][1] += wv.x*av.y; acc[0][2] += wv.x*av.z; acc[0][3] += wv.x*av.w;
            acc[1][0] += wv.y*av.x; acc[1][1] += wv.y*av.y; acc[1][2] += wv.y*av.z; acc[1][3] += wv.y*av.w;
            acc[2][0] += wv.z*av.x; acc[2][1] += wv.z*av.y; acc[2][2] += wv.z*av.z; acc[2][3] += wv.z*av.w;
            acc[3][0] += wv.w*av.x; acc[3][1] += wv.w*av.y; acc[3][2] += wv.w*av.z; acc[3][3] += wv.w*av.w;
        }
        __syncthreads();
    }

    #pragma unroll
    for (int i = 0; i < 4; i++){
        int o = o0 + tx*4 + i;
        float bv = __ldg(&bias[o]);
        float4 r = make_float4(acc[i][0]+bv, acc[i][1]+bv, acc[i][2]+bv, acc[i][3]+bv);
        *(float4*)&out[(size_t)((b*OUTC + o) << 14) + n0 + ty*4] = r;
    }
}

// ---------------- launch -----------------------------------------------------
extern "C" void kernel_launch(void* const* d_in, const int* in_sizes, int n_in,
                              void* d_out, int out_size){
    const float* x      = (const float*)d_in[0];
    const float* w_off  = (const float*)d_in[1];
    const float* b_off  = (const float*)d_in[2];
    const float* weight = (const float*)d_in[3];
    const float* bias   = (const float*)d_in[4];
    float* out = (float*)d_out;

    transpose_kernel<<<dim3(4, 8, 256), dim3(32, 8)>>>(x);
    offs_conv_kernel<<<dim3(128, 2), 128>>>(x, w_off, b_off);
    softmax_kernel<<<18, 256>>>();
    sample_kernel<<<4096, 256>>>();
    gemm_kernel<<<dim3(4, 256, 2), 256>>>(weight, bias, out);
}

// round 14
// speedup vs baseline: 1.2239x; 1.2239x over previous
#include <cuda_runtime.h>
#include <math.h>

#define BATCH 2
#define CIN   256
#define HH    128
#define WW    128
#define OUTC  256
#define HWN   (HH*WW)

typedef unsigned long long ull;

// ---------------- device scratch (no allocations allowed) -------------------
__device__ __align__(16) float  g_xT [BATCH*HWN*CIN];   // x as [b][y][x][c]
__device__ __align__(16) float  g_tmp[BATCH*27*HWN];    // offset conv out [b][27][hw]
__device__ __align__(16) float  g_agg[BATCH*HWN*CIN];   // Sum_k mask*sample [b][hw][c]
__device__ float2 g_mstat[BATCH*9];                     // per (b,k): {rowmax, 1/sum}

// ---------------- packed f32x2 helpers (Blackwell, PTX only) ----------------
__device__ __forceinline__ ull pack2(float lo, float hi){
    ull r; asm("mov.b64 %0,{%1,%2};" : "=l"(r) : "f"(lo), "f"(hi)); return r;
}
__device__ __forceinline__ void unpack2(ull v, float &lo, float &hi){
    asm("mov.b64 {%0,%1},%2;" : "=f"(lo), "=f"(hi) : "l"(v));
}
__device__ __forceinline__ ull ffma2(ull a, ull b, ull c){
    ull d; asm("fma.rn.f32x2 %0,%1,%2,%3;" : "=l"(d) : "l"(a), "l"(b), "l"(c)); return d;
}

// ---------------- 1) NCHW -> NHWC transpose ---------------------------------
__global__ void transpose_kernel(const float* __restrict__ x){
    __shared__ float tile[32][33];
    int b  = blockIdx.z >> 7;
    int y  = blockIdx.z & 127;
    int x0 = blockIdx.x * 32;
    int c0 = blockIdx.y * 32;
    int tx = threadIdx.x, ty = threadIdx.y;
    #pragma unroll
    for (int q = 0; q < 4; q++){
        int c = ty + q*8;
        tile[c][tx] = x[(((b*CIN + c0 + c)*HH + y) << 7) + x0 + tx];
    }
    __syncthreads();
    #pragma unroll
    for (int q = 0; q < 4; q++){
        int xi = ty + q*8;
        g_xT[((((b*HH + y) << 7) + x0 + xi) << 8) + c0 + tx] = tile[tx][xi];
    }
}

// ---------------- 1b) prefill g_tmp with conv bias --------------------------
__global__ void fill_bias_kernel(const float* __restrict__ b_off){
    int i = blockIdx.x * 256 + threadIdx.x;
    if (i < BATCH*27*HWN)
        g_tmp[i] = __ldg(&b_off[(i >> 14) % 27]);
}

// ---------------- 2) offset conv: f32x2 over row pairs, C split x2 ----------
// block: 128 threads = 128 pixel columns; handles rows (y0, y0+1); 128 channels
__global__ __launch_bounds__(128, 2)
void offs_conv_kernel(const float* __restrict__ x,
                      const float* __restrict__ w_off){
    __shared__ __align__(16) float  sx[8][4][132];  // [c][row y0-1..y0+2][x+1 halo]
    __shared__ __align__(16) float2 sw[8][9][28];   // duplicated (w,w), padded 28

    int y0   = blockIdx.x * 2;
    int b    = blockIdx.y;
    int csel = blockIdx.z;              // channel half: [csel*128, csel*128+128)
    int t    = threadIdx.x;             // pixel x

    ull acc[27];
    #pragma unroll
    for (int oc = 0; oc < 27; oc++) acc[oc] = 0ull;

    for (int cc = 0; cc < 128; cc += 8){
        int cb = csel*128 + cc;
        // stage 8 channels x 4 rows (y0-1..y0+2) x 130 cols with zero halo
        for (int i = t; i < 8*4*130; i += 128){
            int xi  = i % 130;
            int rc  = i / 130;
            int row = rc % 4;
            int c   = rc / 4;
            int yy  = y0 - 1 + row;
            int xx  = xi - 1;
            float v = 0.f;
            if (yy >= 0 && yy < HH && xx >= 0 && xx < WW)
                v = x[(((b*CIN + cb + c)*HH + yy) << 7) + xx];
            sx[c][row][xi] = v;
        }
        // stage duplicated weights (w,w)
        for (int e = t; e < 8*9*27; e += 128){
            int oc  = e % 27;
            int rr  = e / 27;
            int tap = rr % 9;
            int c   = rr / 9;
            float wv = w_off[((oc*CIN) + cb + c)*9 + tap];
            sw[c][tap][oc] = make_float2(wv, wv);
        }
        __syncthreads();

        #pragma unroll
        for (int c = 0; c < 8; c++){
            ull vp[9];
            #pragma unroll
            for (int ky = 0; ky < 3; ky++)
                #pragma unroll
                for (int kx = 0; kx < 3; kx++)
                    vp[ky*3+kx] = pack2(sx[c][ky][t+kx], sx[c][ky+1][t+kx]);
            #pragma unroll
            for (int tap = 0; tap < 9; tap++){
                const ulonglong2* wp = (const ulonglong2*)&sw[c][tap][0];
                #pragma unroll
                for (int p = 0; p < 13; p++){
                    ulonglong2 w2 = wp[p];               // 2 dup weights, 1 LDS.128
                    acc[2*p]   = ffma2(vp[tap], w2.x, acc[2*p]);
                    acc[2*p+1] = ffma2(vp[tap], w2.y, acc[2*p+1]);
                }
                ull wl = *(const ull*)&sw[c][tap][26];
                acc[26] = ffma2(vp[tap], wl, acc[26]);
            }
        }
        __syncthreads();
    }

    #pragma unroll
    for (int oc = 0; oc < 27; oc++){
        float p0, p1;
        unpack2(acc[oc], p0, p1);
        float* dst = &g_tmp[((b*27 + oc) << 14) + (y0 << 7) + t];
        atomicAdd(dst,       p0);        // REDG fire-and-forget
        atomicAdd(dst + 128, p1);
    }
}

// ---------------- 3) softmax stats per (b,k) over HW -------------------------
__global__ void softmax_kernel(){
    __shared__ float red[256];
    int bi = blockIdx.x;                     // 0..17
    int t  = threadIdx.x;
    const float* row = g_tmp + (((bi/9)*27 + 18 + (bi%9)) << 14);
    float m = -1e30f;
    for (int i = t; i < HWN; i += 256) m = fmaxf(m, row[i]);
    red[t] = m; __syncthreads();
    for (int s = 128; s > 0; s >>= 1){
        if (t < s) red[t] = fmaxf(red[t], red[t+s]);
        __syncthreads();
    }
    float mx = red[0]; __syncthreads();
    float sacc = 0.f;
    for (int i = t; i < HWN; i += 256) sacc += expf(row[i] - mx);
    red[t] = sacc; __syncthreads();
    for (int s = 128; s > 0; s >>= 1){
        if (t < s) red[t] += red[t+s];
        __syncthreads();
    }
    if (t == 0) g_mstat[bi] = make_float2(mx, 1.0f / red[0]);
}

// ---------------- 4) bilinear sample + mask, summed over K ------------------
__global__ __launch_bounds__(256)
void sample_kernel(){
    int wid  = blockIdx.x * 8 + (threadIdx.x >> 5);
    int lane = threadIdx.x & 31;
    int b    = wid >> 14;
    int hw   = wid & 16383;
    int y    = hw >> 7, xx = hw & 127;

    int   cy0 = 0, cy1 = 0, cx0 = 0, cx1 = 0;
    float W00 = 0.f, W01 = 0.f, W10 = 0.f, W11 = 0.f;
    if (lane < 9){
        int base = (b*27) << 14;
        float dy = g_tmp[base + ((2*lane    ) << 14) + hw];
        float dx = g_tmp[base + ((2*lane + 1) << 14) + hw];
        float mr = g_tmp[base + ((18 + lane ) << 14) + hw];
        float2 st = g_mstat[b*9 + lane];
        float mask = expf(mr - st.x) * st.y;

        float py = dy + (float)(lane/3) - 1.0f + (float)y;
        float px = dx + (float)(lane%3) - 1.0f + (float)xx;
        float fy = floorf(py), fx = floorf(px);
        int   y0 = (int)fy,    x0 = (int)fx;
        float ly = py - fy,    lx = px - fx;

        bool vy0 = (y0 >= 0)     && (y0 < HH);
        bool vy1 = (y0+1 >= 0)   && (y0+1 < HH);
        bool vx0 = (x0 >= 0)     && (x0 < WW);
        bool vx1 = (x0+1 >= 0)   && (x0+1 < WW);

        W00 = (vy0 && vx0) ? (1.f-ly)*(1.f-lx)*mask : 0.f;
        W01 = (vy0 && vx1) ? (1.f-ly)*lx      *mask : 0.f;
        W10 = (vy1 && vx0) ? ly*(1.f-lx)      *mask : 0.f;
        W11 = (vy1 && vx1) ? ly*lx            *mask : 0.f;
        cy0 = min(max(y0,     0), HH-1);
        cy1 = min(max(y0 + 1, 0), HH-1);
        cx0 = min(max(x0,     0), WW-1);
        cx1 = min(max(x0 + 1, 0), WW-1);
    }

    float4 a0 = make_float4(0.f,0.f,0.f,0.f);
    float4 a1 = make_float4(0.f,0.f,0.f,0.f);
    const unsigned FULL = 0xffffffffu;
    int bbase = (b << 14);

    #pragma unroll
    for (int k = 0; k < 9; k++){
        int   ky0 = __shfl_sync(FULL, cy0, k);
        int   ky1 = __shfl_sync(FULL, cy1, k);
        int   kx0 = __shfl_sync(FULL, cx0, k);
        int   kx1 = __shfl_sync(FULL, cx1, k);
        float w00 = __shfl_sync(FULL, W00, k);
        float w01 = __shfl_sync(FULL, W01, k);
        float w10 = __shfl_sync(FULL, W10, k);
        float w11 = __shfl_sync(FULL, W11, k);

        int co = lane << 2;
        if (w00 != 0.f){
            const float* p = g_xT + (((bbase + (ky0<<7) + kx0)) << 8);
            float4 v0 = *(const float4*)(p + co);
            float4 v1 = *(const float4*)(p + 128 + co);
            a0.x += w00*v0.x; a0.y += w00*v0.y; a0.z += w00*v0.z; a0.w += w00*v0.w;
            a1.x += w00*v1.x; a1.y += w00*v1.y; a1.z += w00*v1.z; a1.w += w00*v1.w;
        }
        if (w01 != 0.f){
            const float* p = g_xT + (((bbase + (ky0<<7) + kx1)) << 8);
            float4 v0 = *(const float4*)(p + co);
            float4 v1 = *(const float4*)(p + 128 + co);
            a0.x += w01*v0.x; a0.y += w01*v0.y; a0.z += w01*v0.z; a0.w += w01*v0.w;
            a1.x += w01*v1.x; a1.y += w01*v1.y; a1.z += w01*v1.z; a1.w += w01*v1.w;
        }
        if (w10 != 0.f){
            const float* p = g_xT + (((bbase + (ky1<<7) + kx0)) << 8);
            float4 v0 = *(const float4*)(p + co);
            float4 v1 = *(const float4*)(p + 128 + co);
            a0.x += w10*v0.x; a0.y += w10*v0.y; a0.z += w10*v0.z; a0.w += w10*v0.w;
            a1.x += w10*v1.x; a1.y += w10*v1.y; a1.z += w10*v1.z; a1.w += w10*v1.w;
        }
        if (w11 != 0.f){
            const float* p = g_xT + (((bbase + (ky1<<7) + kx1)) << 8);
            float4 v0 = *(const float4*)(p + co);
            float4 v1 = *(const float4*)(p + 128 + co);
            a0.x += w11*v0.x; a0.y += w11*v0.y; a0.z += w11*v0.z; a0.w += w11*v0.w;
            a1.x += w11*v1.x; a1.y += w11*v1.y; a1.z += w11*v1.z; a1.w += w11*v1.w;
        }
    }

    float* dst = g_agg + ((size_t)wid << 8);
    *(float4*)(dst + (lane<<2))       = a0;
    *(float4*)(dst + 128 + (lane<<2)) = a1;
}

// ---------------- 5) 1x1 GEMM with f32x2 n-pairs -----------------------------
// block 256 thr, tile 64 o x 128 n, microtile 4 o x 8 n (4 packed pairs)
__global__ __launch_bounds__(256)
void gemm_kernel(const float* __restrict__ weight,
                 const float* __restrict__ bias,
                 float* __restrict__ out){
    __shared__ __align__(16) float Ws[16][68];    // [kk][oo]
    __shared__ __align__(16) float As[16][136];   // [kk][nn]

    int o0 = blockIdx.x * 64;
    int n0 = blockIdx.y * 128;
    int b  = blockIdx.z;
    int tid = threadIdx.x;
    int tx = tid & 15;      // o-quad
    int ty = tid >> 4;      // n-oct (0..15)

    ull acc[4][4];
    #pragma unroll
    for (int i = 0; i < 4; i++)
        #pragma unroll
        for (int j = 0; j < 4; j++) acc[i][j] = 0ull;

    int w_o = tid >> 2;           // 0..63
    int w_k = (tid & 3) << 2;     // 0,4,8,12
    int a_n = tid >> 1;           // 0..127
    int a_k = (tid & 1) << 3;     // 0 or 8

    for (int c0 = 0; c0 < CIN; c0 += 16){
        float4 w4 = *(const float4*)&weight[(o0 + w_o)*CIN + c0 + w_k];
        Ws[w_k+0][w_o] = w4.x; Ws[w_k+1][w_o] = w4.y;
        Ws[w_k+2][w_o] = w4.z; Ws[w_k+3][w_o] = w4.w;

        const float* ap = &g_agg[(size_t)((b<<14) + n0 + a_n)*CIN + c0 + a_k];
        float4 a4 = *(const float4*)ap;
        float4 a5 = *(const float4*)(ap + 4);
        As[a_k+0][a_n] = a4.x; As[a_k+1][a_n] = a4.y;
        As[a_k+2][a_n] = a4.z; As[a_k+3][a_n] = a4.w;
        As[a_k+4][a_n] = a5.x; As[a_k+5][a_n] = a5.y;
        As[a_k+6][a_n] = a5.z; As[a_k+7][a_n] = a5.w;
        __syncthreads();

        #pragma unroll
        for (int kk = 0; kk < 16; kk++){
            float4 wv = *(const float4*)&Ws[kk][tx*4];
            ull wd0 = pack2(wv.x, wv.x);
            ull wd1 = pack2(wv.y, wv.y);
            ull wd2 = pack2(wv.z, wv.z);
            ull wd3 = pack2(wv.w, wv.w);
            const ulonglong2* av = (const ulonglong2*)&As[kk][ty*8];
            ulonglong2 av01 = av[0];        // n pairs (0,1),(2,3)
            ulonglong2 av23 = av[1];        // n pairs (4,5),(6,7)
            acc[0][0] = ffma2(wd0, av01.x, acc[0][0]);
            acc[0][1] = ffma2(wd0, av01.y, acc[0][1]);
            acc[0][2] = ffma2(wd0, av23.x, acc[0][2]);
            acc[0][3] = ffma2(wd0, av23.y, acc[0][3]);
            acc[1][0] = ffma2(wd1, av01.x, acc[1][0]);
            acc[1][1] = ffma2(wd1, av01.y, acc[1][1]);
            acc[1][2] = ffma2(wd1, av23.x, acc[1][2]);
            acc[1][3] = ffma2(wd1, av23.y, acc[1][3]);
            acc[2][0] = ffma2(wd2, av01.x, acc[2][0]);
            acc[2][1] = ffma2(wd2, av01.y, acc[2][1]);
            acc[2][2] = ffma2(wd2, av23.x, acc[2][2]);
            acc[2][3] = ffma2(wd2, av23.y, acc[2][3]);
            acc[3][0] = ffma2(wd3, av01.x, acc[3][0]);
            acc[3][1] = ffma2(wd3, av01.y, acc[3][1]);
            acc[3][2] = ffma2(wd3, av23.x, acc[3][2]);
            acc[3][3] = ffma2(wd3, av23.y, acc[3][3]);
        }
        __syncthreads();
    }

    #pragma unroll
    for (int i = 0; i < 4; i++){
        int o = o0 + tx*4 + i;
        float bv = __ldg(&bias[o]);
        float r[8];
        #pragma unroll
        for (int j = 0; j < 4; j++){
            float lo, hi;
            unpack2(acc[i][j], lo, hi);
            r[2*j]   = lo + bv;
            r[2*j+1] = hi + bv;
        }
        float* dp = &out[(size_t)((b*OUTC + o) << 14) + n0 + ty*8];
        *(float4*)dp       = make_float4(r[0], r[1], r[2], r[3]);
        *(float4*)(dp + 4) = make_float4(r[4], r[5], r[6], r[7]);
    }
}

// ---------------- launch -----------------------------------------------------
extern "C" void kernel_launch(void* const* d_in, const int* in_sizes, int n_in,
                              void* d_out, int out_size){
    const float* x      = (const float*)d_in[0];
    const float* w_off  = (const float*)d_in[1];
    const float* b_off  = (const float*)d_in[2];
    const float* weight = (const float*)d_in[3];
    const float* bias   = (const float*)d_in[4];
    float* out = (float*)d_out;

    fill_bias_kernel<<<(BATCH*27*HWN + 255)/256, 256>>>(b_off);
    transpose_kernel<<<dim3(4, 8, 256), dim3(32, 8)>>>(x);
    offs_conv_kernel<<<dim3(64, BATCH, 2), 128>>>(x, w_off);
    softmax_kernel<<<18, 256>>>();
    sample_kernel<<<4096, 256>>>();
    gemm_kernel<<<dim3(4, 128, BATCH), 256>>>(weight, bias, out);
}

// round 15
// speedup vs baseline: 1.2270x; 1.0025x over previous
#include <cuda_runtime.h>
#include <math.h>

#define BATCH 2
#define CIN   256
#define HH    128
#define WW    128
#define OUTC  256
#define HWN   (HH*WW)

typedef unsigned long long ull;

// ---------------- device scratch (no allocations allowed) -------------------
__device__ __align__(16) float  g_xT [BATCH*HWN*CIN];   // x as [b][y][x][c]
__device__ __align__(16) float  g_tmp[BATCH*27*HWN];    // offset conv out [b][27][hw]
__device__ __align__(16) float  g_agg[BATCH*HWN*CIN];   // Sum_k mask*sample [b][hw][c]
__device__ float2 g_mstat[BATCH*9];                     // per (b,k): {rowmax, 1/sum}

// ---------------- packed f32x2 helpers (Blackwell, PTX only) ----------------
__device__ __forceinline__ ull pack2(float lo, float hi){
    ull r; asm("mov.b64 %0,{%1,%2};" : "=l"(r) : "f"(lo), "f"(hi)); return r;
}
__device__ __forceinline__ void unpack2(ull v, float &lo, float &hi){
    asm("mov.b64 {%0,%1},%2;" : "=f"(lo), "=f"(hi) : "l"(v));
}
__device__ __forceinline__ ull ffma2(ull a, ull b, ull c){
    ull d; asm("fma.rn.f32x2 %0,%1,%2,%3;" : "=l"(d) : "l"(a), "l"(b), "l"(c)); return d;
}

// ---------------- 1) NCHW -> NHWC transpose ---------------------------------
__global__ void transpose_kernel(const float* __restrict__ x){
    __shared__ float tile[32][33];
    int b  = blockIdx.z >> 7;
    int y  = blockIdx.z & 127;
    int x0 = blockIdx.x * 32;
    int c0 = blockIdx.y * 32;
    int tx = threadIdx.x, ty = threadIdx.y;
    #pragma unroll
    for (int q = 0; q < 4; q++){
        int c = ty + q*8;
        tile[c][tx] = x[(((b*CIN + c0 + c)*HH + y) << 7) + x0 + tx];
    }
    __syncthreads();
    #pragma unroll
    for (int q = 0; q < 4; q++){
        int xi = ty + q*8;
        g_xT[((((b*HH + y) << 7) + x0 + xi) << 8) + c0 + tx] = tile[tx][xi];
    }
}

// ---------------- 1b) prefill g_tmp with conv bias --------------------------
__global__ void fill_bias_kernel(const float* __restrict__ b_off){
    int i = blockIdx.x * 256 + threadIdx.x;
    if (i < BATCH*27*HWN)
        g_tmp[i] = __ldg(&b_off[(i >> 14) % 27]);
}

// ---------------- 2) offset conv: f32x2 over row pairs, C split x2 ----------
// block: 128 threads = 128 pixel columns; handles rows (y0, y0+1); 128 channels
__global__ __launch_bounds__(128, 2)
void offs_conv_kernel(const float* __restrict__ x,
                      const float* __restrict__ w_off){
    __shared__ __align__(16) float  sx[8][4][132];  // [c][row y0-1..y0+2][x+1 halo]
    __shared__ __align__(16) float2 sw[8][9][28];   // duplicated (w,w), padded 28

    int y0   = blockIdx.x * 2;
    int b    = blockIdx.y;
    int csel = blockIdx.z;              // channel half: [csel*128, csel*128+128)
    int t    = threadIdx.x;             // pixel x

    ull acc[27];
    #pragma unroll
    for (int oc = 0; oc < 27; oc++) acc[oc] = 0ull;

    for (int cc = 0; cc < 128; cc += 8){
        int cb = csel*128 + cc;
        // stage 8 channels x 4 rows (y0-1..y0+2) x 130 cols with zero halo
        for (int i = t; i < 8*4*130; i += 128){
            int xi  = i % 130;
            int rc  = i / 130;
            int row = rc % 4;
            int c   = rc / 4;
            int yy  = y0 - 1 + row;
            int xx  = xi - 1;
            float v = 0.f;
            if (yy >= 0 && yy < HH && xx >= 0 && xx < WW)
                v = x[(((b*CIN + cb + c)*HH + yy) << 7) + xx];
            sx[c][row][xi] = v;
        }
        // stage duplicated weights (w,w)
        for (int e = t; e < 8*9*27; e += 128){
            int oc  = e % 27;
            int rr  = e / 27;
            int tap = rr % 9;
            int c   = rr / 9;
            float wv = w_off[((oc*CIN) + cb + c)*9 + tap];
            sw[c][tap][oc] = make_float2(wv, wv);
        }
        __syncthreads();

        #pragma unroll
        for (int c = 0; c < 8; c++){
            ull vp[9];
            #pragma unroll
            for (int ky = 0; ky < 3; ky++)
                #pragma unroll
                for (int kx = 0; kx < 3; kx++)
                    vp[ky*3+kx] = pack2(sx[c][ky][t+kx], sx[c][ky+1][t+kx]);
            #pragma unroll
            for (int tap = 0; tap < 9; tap++){
                const ulonglong2* wp = (const ulonglong2*)&sw[c][tap][0];
                #pragma unroll
                for (int p = 0; p < 13; p++){
                    ulonglong2 w2 = wp[p];               // 2 dup weights, 1 LDS.128
                    acc[2*p]   = ffma2(vp[tap], w2.x, acc[2*p]);
                    acc[2*p+1] = ffma2(vp[tap], w2.y, acc[2*p+1]);
                }
                ull wl = *(const ull*)&sw[c][tap][26];
                acc[26] = ffma2(vp[tap], wl, acc[26]);
            }
        }
        __syncthreads();
    }

    #pragma unroll
    for (int oc = 0; oc < 27; oc++){
        float p0, p1;
        unpack2(acc[oc], p0, p1);
        float* dst = &g_tmp[((b*27 + oc) << 14) + (y0 << 7) + t];
        atomicAdd(dst,       p0);        // REDG fire-and-forget
        atomicAdd(dst + 128, p1);
    }
}

// ---------------- 3) softmax stats per (b,k) over HW -------------------------
__global__ void softmax_kernel(){
    __shared__ float red[256];
    int bi = blockIdx.x;                     // 0..17
    int t  = threadIdx.x;
    const float* row = g_tmp + (((bi/9)*27 + 18 + (bi%9)) << 14);
    float m = -1e30f;
    for (int i = t; i < HWN; i += 256) m = fmaxf(m, row[i]);
    red[t] = m; __syncthreads();
    for (int s = 128; s > 0; s >>= 1){
        if (t < s) red[t] = fmaxf(red[t], red[t+s]);
        __syncthreads();
    }
    float mx = red[0]; __syncthreads();
    float sacc = 0.f;
    for (int i = t; i < HWN; i += 256) sacc += expf(row[i] - mx);
    red[t] = sacc; __syncthreads();
    for (int s = 128; s > 0; s >>= 1){
        if (t < s) red[t] += red[t+s];
        __syncthreads();
    }
    if (t == 0) g_mstat[bi] = make_float2(mx, 1.0f / red[0]);
}

// ---------------- 4) bilinear sample + mask, summed over K ------------------
__global__ __launch_bounds__(256)
void sample_kernel(){
    int wid  = blockIdx.x * 8 + (threadIdx.x >> 5);
    int lane = threadIdx.x & 31;
    int b    = wid >> 14;
    int hw   = wid & 16383;
    int y    = hw >> 7, xx = hw & 127;

    int   cy0 = 0, cy1 = 0, cx0 = 0, cx1 = 0;
    float W00 = 0.f, W01 = 0.f, W10 = 0.f, W11 = 0.f;
    if (lane < 9){
        int base = (b*27) << 14;
        float dy = g_tmp[base + ((2*lane    ) << 14) + hw];
        float dx = g_tmp[base + ((2*lane + 1) << 14) + hw];
        float mr = g_tmp[base + ((18 + lane ) << 14) + hw];
        float2 st = g_mstat[b*9 + lane];
        float mask = expf(mr - st.x) * st.y;

        float py = dy + (float)(lane/3) - 1.0f + (float)y;
        float px = dx + (float)(lane%3) - 1.0f + (float)xx;
        float fy = floorf(py), fx = floorf(px);
        int   y0 = (int)fy,    x0 = (int)fx;
        float ly = py - fy,    lx = px - fx;

        bool vy0 = (y0 >= 0)     && (y0 < HH);
        bool vy1 = (y0+1 >= 0)   && (y0+1 < HH);
        bool vx0 = (x0 >= 0)     && (x0 < WW);
        bool vx1 = (x0+1 >= 0)   && (x0+1 < WW);

        W00 = (vy0 && vx0) ? (1.f-ly)*(1.f-lx)*mask : 0.f;
        W01 = (vy0 && vx1) ? (1.f-ly)*lx      *mask : 0.f;
        W10 = (vy1 && vx0) ? ly*(1.f-lx)      *mask : 0.f;
        W11 = (vy1 && vx1) ? ly*lx            *mask : 0.f;
        cy0 = min(max(y0,     0), HH-1);
        cy1 = min(max(y0 + 1, 0), HH-1);
        cx0 = min(max(x0,     0), WW-1);
        cx1 = min(max(x0 + 1, 0), WW-1);
    }

    float4 a0 = make_float4(0.f,0.f,0.f,0.f);
    float4 a1 = make_float4(0.f,0.f,0.f,0.f);
    const unsigned FULL = 0xffffffffu;
    int bbase = (b << 14);

    #pragma unroll
    for (int k = 0; k < 9; k++){
        int   ky0 = __shfl_sync(FULL, cy0, k);
        int   ky1 = __shfl_sync(FULL, cy1, k);
        int   kx0 = __shfl_sync(FULL, cx0, k);
        int   kx1 = __shfl_sync(FULL, cx1, k);
        float w00 = __shfl_sync(FULL, W00, k);
        float w01 = __shfl_sync(FULL, W01, k);
        float w10 = __shfl_sync(FULL, W10, k);
        float w11 = __shfl_sync(FULL, W11, k);

        int co = lane << 2;
        if (w00 != 0.f){
            const float* p = g_xT + (((bbase + (ky0<<7) + kx0)) << 8);
            float4 v0 = *(const float4*)(p + co);
            float4 v1 = *(const float4*)(p + 128 + co);
            a0.x += w00*v0.x; a0.y += w00*v0.y; a0.z += w00*v0.z; a0.w += w00*v0.w;
            a1.x += w00*v1.x; a1.y += w00*v1.y; a1.z += w00*v1.z; a1.w += w00*v1.w;
        }
        if (w01 != 0.f){
            const float* p = g_xT + (((bbase + (ky0<<7) + kx1)) << 8);
            float4 v0 = *(const float4*)(p + co);
            float4 v1 = *(const float4*)(p + 128 + co);
            a0.x += w01*v0.x; a0.y += w01*v0.y; a0.z += w01*v0.z; a0.w += w01*v0.w;
            a1.x += w01*v1.x; a1.y += w01*v1.y; a1.z += w01*v1.z; a1.w += w01*v1.w;
        }
        if (w10 != 0.f){
            const float* p = g_xT + (((bbase + (ky1<<7) + kx0)) << 8);
            float4 v0 = *(const float4*)(p + co);
            float4 v1 = *(const float4*)(p + 128 + co);
            a0.x += w10*v0.x; a0.y += w10*v0.y; a0.z += w10*v0.z; a0.w += w10*v0.w;
            a1.x += w10*v1.x; a1.y += w10*v1.y; a1.z += w10*v1.z; a1.w += w10*v1.w;
        }
        if (w11 != 0.f){
            const float* p = g_xT + (((bbase + (ky1<<7) + kx1)) << 8);
            float4 v0 = *(const float4*)(p + co);
            float4 v1 = *(const float4*)(p + 128 + co);
            a0.x += w11*v0.x; a0.y += w11*v0.y; a0.z += w11*v0.z; a0.w += w11*v0.w;
            a1.x += w11*v1.x; a1.y += w11*v1.y; a1.z += w11*v1.z; a1.w += w11*v1.w;
        }
    }

    float* dst = g_agg + ((size_t)wid << 8);
    *(float4*)(dst + (lane<<2))       = a0;
    *(float4*)(dst + 128 + (lane<<2)) = a1;
}

// ---------------- 5) 1x1 GEMM with f32x2 n-pairs -----------------------------
// block 256 thr, tile 64 o x 128 n, microtile 4 o x 8 n (4 packed pairs)
__global__ __launch_bounds__(256)
void gemm_kernel(const float* __restrict__ weight,
                 const float* __restrict__ bias,
                 float* __restrict__ out){
    __shared__ __align__(16) float Ws[16][68];    // [kk][oo]
    __shared__ __align__(16) float As[16][136];   // [kk][nn]

    int o0 = blockIdx.x * 64;
    int n0 = blockIdx.y * 128;
    int b  = blockIdx.z;
    int tid = threadIdx.x;
    int tx = tid & 15;      // o-quad
    int ty = tid >> 4;      // n-oct (0..15)

    ull acc[4][4];
    #pragma unroll
    for (int i = 0; i < 4; i++)
        #pragma unroll
        for (int j = 0; j < 4; j++) acc[i][j] = 0ull;

    int w_o = tid >> 2;           // 0..63
    int w_k = (tid & 3) << 2;     // 0,4,8,12
    int a_n = tid >> 1;           // 0..127
    int a_k = (tid & 1) << 3;     // 0 or 8

    for (int c0 = 0; c0 < CIN; c0 += 16){
        float4 w4 = *(const float4*)&weight[(o0 + w_o)*CIN + c0 + w_k];
        Ws[w_k+0][w_o] = w4.x; Ws[w_k+1][w_o] = w4.y;
        Ws[w_k+2][w_o] = w4.z; Ws[w_k+3][w_o] = w4.w;

        const float* ap = &g_agg[(size_t)((b<<14) + n0 + a_n)*CIN + c0 + a_k];
        float4 a4 = *(const float4*)ap;
        float4 a5 = *(const float4*)(ap + 4);
        As[a_k+0][a_n] = a4.x; As[a_k+1][a_n] = a4.y;
        As[a_k+2][a_n] = a4.z; As[a_k+3][a_n] = a4.w;
        As[a_k+4][a_n] = a5.x; As[a_k+5][a_n] = a5.y;
        As[a_k+6][a_n] = a5.z; As[a_k+7][a_n] = a5.w;
        __syncthreads();

        #pragma unroll
        for (int kk = 0; kk < 16; kk++){
            float4 wv = *(const float4*)&Ws[kk][tx*4];
            ull wd0 = pack2(wv.x, wv.x);
            ull wd1 = pack2(wv.y, wv.y);
            ull wd2 = pack2(wv.z, wv.z);
            ull wd3 = pack2(wv.w, wv.w);
            const ulonglong2* av = (const ulonglong2*)&As[kk][ty*8];
            ulonglong2 av01 = av[0];        // n pairs (0,1),(2,3)
            ulonglong2 av23 = av[1];        // n pairs (4,5),(6,7)
            acc[0][0] = ffma2(wd0, av01.x, acc[0][0]);
            acc[0][1] = ffma2(wd0, av01.y, acc[0][1]);
            acc[0][2] = ffma2(wd0, av23.x, acc[0][2]);
            acc[0][3] = ffma2(wd0, av23.y, acc[0][3]);
            acc[1][0] = ffma2(wd1, av01.x, acc[1][0]);
            acc[1][1] = ffma2(wd1, av01.y, acc[1][1]);
            acc[1][2] = ffma2(wd1, av23.x, acc[1][2]);
            acc[1][3] = ffma2(wd1, av23.y, acc[1][3]);
            acc[2][0] = ffma2(wd2, av01.x, acc[2][0]);
            acc[2][1] = ffma2(wd2, av01.y, acc[2][1]);
            acc[2][2] = ffma2(wd2, av23.x, acc[2][2]);
            acc[2][3] = ffma2(wd2, av23.y, acc[2][3]);
            acc[3][0] = ffma2(wd3, av01.x, acc[3][0]);
            acc[3][1] = ffma2(wd3, av01.y, acc[3][1]);
            acc[3][2] = ffma2(wd3, av23.x, acc[3][2]);
            acc[3][3] = ffma2(wd3, av23.y, acc[3][3]);
        }
        __syncthreads();
    }

    #pragma unroll
    for (int i = 0; i < 4; i++){
        int o = o0 + tx*4 + i;
        float bv = __ldg(&bias[o]);
        float r[8];
        #pragma unroll
        for (int j = 0; j < 4; j++){
            float lo, hi;
            unpack2(acc[i][j], lo, hi);
            r[2*j]   = lo + bv;
            r[2*j+1] = hi + bv;
        }
        float* dp = &out[(size_t)((b*OUTC + o) << 14) + n0 + ty*8];
        *(float4*)dp       = make_float4(r[0], r[1], r[2], r[3]);
        *(float4*)(dp + 4) = make_float4(r[4], r[5], r[6], r[7]);
    }
}

// ---------------- launch -----------------------------------------------------
extern "C" void kernel_launch(void* const* d_in, const int* in_sizes, int n_in,
                              void* d_out, int out_size){
    const float* x      = (const float*)d_in[0];
    const float* w_off  = (const float*)d_in[1];
    const float* b_off  = (const float*)d_in[2];
    const float* weight = (const float*)d_in[3];
    const float* bias   = (const float*)d_in[4];
    float* out = (float*)d_out;

    fill_bias_kernel<<<(BATCH*27*HWN + 255)/256, 256>>>(b_off);
    transpose_kernel<<<dim3(4, 8, 256), dim3(32, 8)>>>(x);
    offs_conv_kernel<<<dim3(64, BATCH, 2), 128>>>(x, w_off);
    softmax_kernel<<<18, 256>>>();
    sample_kernel<<<4096, 256>>>();
    gemm_kernel<<<dim3(4, 128, BATCH), 256>>>(weight, bias, out);
}